// round 8
// baseline (speedup 1.0000x reference)
#include <cuda_runtime.h>
#include <cuda_fp16.h>
#include <math.h>
#include <stdint.h>

// Problem constants
#define SS   1024
#define BB   8
#define HH   1024
#define LL   6
#define FFD  4096
#define MR   (SS*BB)

// ---------------------------------------------------------------------------
// Scratch (static device globals; no allocation anywhere)
// ---------------------------------------------------------------------------
__device__ float  g_x  [MR*HH];              // residual stream fp32
__device__ __half g_xh [MR*HH];              // fp16 copy of x
__device__ __half g_qkv[(long)MR*3*HH];      // packed q|k|v per row (fp16)
__device__ __half g_ct [MR*HH];              // ctx (fp16)
__device__ float  g_t  [MR*HH];              // residual branch fp32
__device__ __half g_vt [(long)BB*HH*SS];     // V transposed (B,H,S) fp16
__device__ float  g_sc [(long)BB*SS*SS];     // attention scores fp32
__device__ __half g_sch[(long)BB*SS*SS];     // softmax probs fp16
__device__ __half g_ffh[(long)MR*FFD];       // ff hidden fp16
__device__ __half g_wTh[75497472];           // transposed fp16 weights
__device__ float  g_b3 [LL*3*HH];            // packed qkv bias (bq/32|bk|bv)

// offsets (elements) inside g_wTh
#define QKVT 0L                                  // [L][3][H][H]
#define WOT  (18L*HH*HH)
#define W1T  (WOT + 6L*HH*HH)
#define W2T  (W1T + 6L*HH*FFD)

// ---------------------------------------------------------------------------
// fp16 tensor-core GEMM (mma.sync m16n8k16, fp32 accumulate, ldmatrix frags)
//   C[z] = (A[z] @ B[z]^T + bias) * alpha  (+ optional ReLU)
// A: M x K row-major fp16 (lda). B: N x K row-major fp16 (ldb).
// OUTH=1 -> C fp16 ; OUTH=0 -> C fp32.
// Block tile 256x128x32, 8 warps (warp tile 64x64), 4-stage cp.async ring.
// M % 256 == 0, N % 128 == 0, K % 32 == 0.
// ---------------------------------------------------------------------------
__device__ __forceinline__ void mma16816(float* d, const uint32_t* a,
                                         uint32_t b0, uint32_t b1) {
    asm volatile(
        "mma.sync.aligned.m16n8k16.row.col.f32.f16.f16.f32 "
        "{%0,%1,%2,%3}, {%4,%5,%6,%7}, {%8,%9}, {%0,%1,%2,%3};"
        : "+f"(d[0]), "+f"(d[1]), "+f"(d[2]), "+f"(d[3])
        : "r"(a[0]), "r"(a[1]), "r"(a[2]), "r"(a[3]), "r"(b0), "r"(b1));
}
__device__ __forceinline__ void ldsm4(uint32_t* r, uint32_t addr) {
    asm volatile("ldmatrix.sync.aligned.m8n8.x4.shared.b16 {%0,%1,%2,%3}, [%4];"
                 : "=r"(r[0]), "=r"(r[1]), "=r"(r[2]), "=r"(r[3]) : "r"(addr));
}
__device__ __forceinline__ void cpa16(uint32_t dst, const void* src) {
    asm volatile("cp.async.cg.shared.global [%0], [%1], 16;" :: "r"(dst), "l"(src));
}
#define CP_COMMIT() asm volatile("cp.async.commit_group;" ::: "memory")
#define CP_WAIT(n)  asm volatile("cp.async.wait_group %0;" :: "n"(n) : "memory")

#define LDW     20                        // uint32 words/row (16 data + 4 pad)
#define STAGES  4
#define BM      256
#define BN      128
#define STG_W   ((BM + BN) * LDW)         // words per stage (A + B)
#define STG_B   (STG_W * 4u)              // bytes per stage
#define BOFF_B  ((uint32_t)BM * LDW * 4u) // B tile byte offset within stage
#define GEMM_SMEM (STAGES * STG_W * 4)    // 122880 bytes

template<int OUTH, int RELU>
__global__ void __launch_bounds__(256, 1)
gemmh(const __half* __restrict__ A, long sA, int lda,
      const __half* __restrict__ B, long sB, int ldb,
      const float* __restrict__ bias,
      void* __restrict__ Cv, long sC, int ldc,
      int K, float alpha)
{
    extern __shared__ __align__(16) uint32_t sm[];
    const uint32_t sbase = (uint32_t)__cvta_generic_to_shared(sm);

    A += (long)blockIdx.z * sA;
    B += (long)blockIdx.z * sB;
    __half* Ch = (__half*)Cv + (OUTH ? (long)blockIdx.z * sC : 0);
    float*  Cf = (float*) Cv + (OUTH ? 0 : (long)blockIdx.z * sC);

    const int bm = blockIdx.y * BM, bn = blockIdx.x * BN;
    const int tid = threadIdx.x;
    const int wid = tid >> 5, lane = tid & 31;
    const int wm = (wid >> 1) * 64, wn = (wid & 1) * 64;   // 4 x 2 warp grid
    const int r = lane >> 2, c = lane & 3;

    float acc[4][8][4];
    #pragma unroll
    for (int im = 0; im < 4; im++)
        #pragma unroll
        for (int jn = 0; jn < 8; jn++)
            #pragma unroll
            for (int q = 0; q < 4; q++) acc[im][jn][q] = 0.f;

    // cp.async staging:
    //   A: each thread owns one full row (4 x 16B chunks): row = tid
    //   B: two threads per row (2 chunks each): row = tid>>1, chunks (tid&1)*2..+1
    const __half* ArowP = A + (long)(bm + tid) * lda;
    const int browB = tid >> 1;
    const int cchB  = (tid & 1) * 2;
    const __half* BrowP = B + (long)(bn + browB) * ldb;
    const uint32_t adst = sbase + (uint32_t)(tid * LDW) * 4u;
    const uint32_t bdst = sbase + BOFF_B + (uint32_t)(browB * LDW + cchB * 4) * 4u;

    auto issue = [&](int t) {
        const uint32_t so = (uint32_t)(t % STAGES) * STG_B;
        const long k0 = (long)t * 32;
        #pragma unroll
        for (int j = 0; j < 4; j++)
            cpa16(adst + so + (uint32_t)j * 16u, ArowP + k0 + j * 8);
        cpa16(bdst + so,       BrowP + k0 + cchB * 8);
        cpa16(bdst + so + 16u, BrowP + k0 + (cchB + 1) * 8);
        CP_COMMIT();
    };

    // ldmatrix base addresses (same lane maps as validated round-7 kernel):
    // A x4 (16x16): lanes 0-15 -> row wm+(lane&15), lanes 16-31 -> +16B k-chunk
    const uint32_t aAddr = sbase
        + (uint32_t)((wm + (lane & 15)) * LDW) * 4u + (uint32_t)(lane >> 4) * 16u;
    // B x4 (two 8-row n-tiles x two k-chunks)
    const uint32_t bAddr = sbase + BOFF_B
        + (uint32_t)((wn + (lane & 7) + ((lane >> 4) << 3)) * LDW) * 4u
        + (uint32_t)((lane >> 3) & 1) * 16u;

    const int nt = K / 32;
    #pragma unroll
    for (int t = 0; t < STAGES - 1; t++) {
        if (t < nt) issue(t); else CP_COMMIT();
    }

    for (int t = 0; t < nt; t++) {
        CP_WAIT(STAGES - 2);
        __syncthreads();
        if (t + STAGES - 1 < nt) issue(t + STAGES - 1);
        else CP_COMMIT();

        const uint32_t so = (uint32_t)(t % STAGES) * STG_B;
        #pragma unroll
        for (int ks = 0; ks < 2; ks++) {
            const uint32_t ko = so + (uint32_t)ks * 32u;   // ks*8 words
            uint32_t a[4][4];
            #pragma unroll
            for (int im = 0; im < 4; im++)
                ldsm4(a[im], aAddr + ko + (uint32_t)im * (16u * LDW * 4u));
            #pragma unroll
            for (int jp = 0; jp < 4; jp++) {
                uint32_t b[4];
                ldsm4(b, bAddr + ko + (uint32_t)jp * (16u * LDW * 4u));
                #pragma unroll
                for (int im = 0; im < 4; im++) {
                    mma16816(acc[im][2*jp    ], a[im], b[0], b[1]);
                    mma16816(acc[im][2*jp + 1], a[im], b[2], b[3]);
                }
            }
        }
    }

    // epilogue: bias -> alpha -> relu
    #pragma unroll
    for (int im = 0; im < 4; im++) {
        #pragma unroll
        for (int jn = 0; jn < 8; jn++) {
            int m = bm + wm + im * 16 + r;
            int n = bn + wn + jn * 8 + 2 * c;
            float v0 = acc[im][jn][0], v1 = acc[im][jn][1];
            float v2 = acc[im][jn][2], v3 = acc[im][jn][3];
            if (bias) {
                float bb0 = bias[n], bb1 = bias[n + 1];
                v0 += bb0; v1 += bb1; v2 += bb0; v3 += bb1;
            }
            v0 *= alpha; v1 *= alpha; v2 *= alpha; v3 *= alpha;
            if (RELU) {
                v0 = fmaxf(v0, 0.f); v1 = fmaxf(v1, 0.f);
                v2 = fmaxf(v2, 0.f); v3 = fmaxf(v3, 0.f);
            }
            if (OUTH) {
                *(__half2*)&Ch[(long)m * ldc + n] = __floats2half2_rn(v0, v1);
                *(__half2*)&Ch[(long)(m + 8) * ldc + n] = __floats2half2_rn(v2, v3);
            } else {
                *(float2*)&Cf[(long)m * ldc + n] = make_float2(v0, v1);
                *(float2*)&Cf[(long)(m + 8) * ldc + n] = make_float2(v2, v3);
            }
        }
    }
}

// ---------------------------------------------------------------------------
// Transposes / packing
// ---------------------------------------------------------------------------
__global__ void transpose_mat_h(const float* __restrict__ src, __half* __restrict__ dst,
                                int R, int C, long zdst, float scale) {
    __shared__ float t[32][33];
    long z = blockIdx.z;
    src += z * (long)R * C;
    dst += z * zdst;
    int r0 = blockIdx.y * 32, c0 = blockIdx.x * 32;
    int x = threadIdx.x, y = threadIdx.y;
    #pragma unroll
    for (int i = 0; i < 32; i += 8)
        t[y + i][x] = src[(long)(r0 + y + i) * C + c0 + x];
    __syncthreads();
    #pragma unroll
    for (int i = 0; i < 32; i += 8)
        dst[(long)(c0 + y + i) * R + r0 + x] = __float2half_rn(t[x][y + i] * scale);
}

__global__ void pack_b3(const float* __restrict__ bq, const float* __restrict__ bk,
                        const float* __restrict__ bv, float* __restrict__ b3) {
    int i = blockIdx.x * 256 + threadIdx.x;
    if (i >= LL * 3 * HH) return;
    int l = i / (3 * HH), j = i % (3 * HH);
    float v;
    if (j < HH)          v = bq[l * HH + j] * (1.0f / 32.0f);
    else if (j < 2 * HH) v = bk[l * HH + j - HH];
    else                 v = bv[l * HH + j - 2 * HH];
    b3[i] = v;
}

// vT[b][h][s] = qkv[(s*B+b)*3H + 2H + h]
__global__ void transpose_v_h(const __half* __restrict__ qkv, __half* __restrict__ vt) {
    __shared__ __half t[32][34];
    int b = blockIdx.z;
    int s0 = blockIdx.y * 32, h0 = blockIdx.x * 32;
    int x = threadIdx.x, y = threadIdx.y;
    #pragma unroll
    for (int i = 0; i < 32; i += 8)
        t[y + i][x] = qkv[((long)(s0 + y + i) * BB + b) * 3 * HH + 2 * HH + h0 + x];
    __syncthreads();
    #pragma unroll
    for (int i = 0; i < 32; i += 8)
        vt[((long)b * HH + h0 + y + i) * SS + s0 + x] = t[x][y + i];
}

// ---------------------------------------------------------------------------
// Embedding + positional encoding (fp32 + fp16)
// ---------------------------------------------------------------------------
__global__ void embed_pe(const int* __restrict__ src,
                         const float* __restrict__ emb,
                         float* __restrict__ x, __half* __restrict__ xh) {
    int row = blockIdx.x;
    int s = row / BB;
    int tok = src[row];
    const float cc = -logf(10000.0f) / (float)HH;
    for (int h = threadIdx.x; h < HH; h += blockDim.x) {
        int i2 = (h >> 1) << 1;
        float div = expf(cc * (float)i2);
        float ang = (float)s * div;
        float pe = (h & 1) ? cosf(ang) : sinf(ang);
        float u = emb[(long)tok * HH + h] * 32.0f + pe;
        x [(long)row * HH + h] = u;
        xh[(long)row * HH + h] = __float2half_rn(u);
    }
}

// ---------------------------------------------------------------------------
// Reductions + softmax + add&LayerNorm
// ---------------------------------------------------------------------------
__device__ __forceinline__ float warpSum(float v) {
    #pragma unroll
    for (int o = 16; o; o >>= 1) v += __shfl_xor_sync(0xffffffffu, v, o);
    return v;
}
__device__ __forceinline__ float warpMax(float v) {
    #pragma unroll
    for (int o = 16; o; o >>= 1) v = fmaxf(v, __shfl_xor_sync(0xffffffffu, v, o));
    return v;
}
__device__ float blockSum(float v) {
    __shared__ float s[8];
    int lane = threadIdx.x & 31, w = threadIdx.x >> 5;
    v = warpSum(v);
    if (!lane) s[w] = v;
    __syncthreads();
    float r;
    if (w == 0) {
        float t = (lane < 8) ? s[lane] : 0.f;
        #pragma unroll
        for (int o = 4; o; o >>= 1) t += __shfl_xor_sync(0xffffffffu, t, o);
        if (!lane) s[0] = t;
    }
    __syncthreads();
    r = s[0];
    __syncthreads();
    return r;
}
__device__ float blockMax(float v) {
    __shared__ float s[8];
    int lane = threadIdx.x & 31, w = threadIdx.x >> 5;
    v = warpMax(v);
    if (!lane) s[w] = v;
    __syncthreads();
    float r;
    if (w == 0) {
        float t = (lane < 8) ? s[lane] : -3.0e38f;
        #pragma unroll
        for (int o = 4; o; o >>= 1) t = fmaxf(t, __shfl_xor_sync(0xffffffffu, t, o));
        if (!lane) s[0] = t;
    }
    __syncthreads();
    r = s[0];
    __syncthreads();
    return r;
}

__global__ void softmax_rows(const float* __restrict__ sc, __half* __restrict__ ph) {
    long row = blockIdx.x;
    const float* p = sc + row * SS;
    __half* o = ph + row * SS;
    int t = threadIdx.x;
    float v[4];
    float mx = -3.0e38f;
    #pragma unroll
    for (int j = 0; j < 4; j++) { v[j] = p[t + j * 256]; mx = fmaxf(mx, v[j]); }
    mx = blockMax(mx);
    float sum = 0.f;
    #pragma unroll
    for (int j = 0; j < 4; j++) { v[j] = expf(v[j] - mx); sum += v[j]; }
    sum = blockSum(sum);
    float inv = 1.0f / sum;
    #pragma unroll
    for (int j = 0; j < 4; j++) o[t + j * 256] = __float2half_rn(v[j] * inv);
}

__global__ void add_ln(const float* __restrict__ x, const float* __restrict__ y,
                       const float* __restrict__ g, const float* __restrict__ b,
                       float* __restrict__ out, __half* __restrict__ outh) {
    long row = blockIdx.x;
    const float* px = x + row * HH;
    const float* py = y ? y + row * HH : nullptr;
    int t = threadIdx.x;
    float v[4];
    float sum = 0.f;
    #pragma unroll
    for (int j = 0; j < 4; j++) {
        float u = px[t + j * 256];
        if (py) u += py[t + j * 256];
        v[j] = u; sum += u;
    }
    sum = blockSum(sum);
    float m = sum * (1.0f / HH);
    float ss = 0.f;
    #pragma unroll
    for (int j = 0; j < 4; j++) { float d = v[j] - m; ss += d * d; }
    ss = blockSum(ss);
    float inv = rsqrtf(ss * (1.0f / HH) + 1e-5f);
    #pragma unroll
    for (int j = 0; j < 4; j++) {
        int h = t + j * 256;
        float o = (v[j] - m) * inv * g[h] + b[h];
        out[row * HH + h] = o;
        if (outh) outh[row * HH + h] = __float2half_rn(o);
    }
}

// ---------------------------------------------------------------------------
// Launcher
// ---------------------------------------------------------------------------
extern "C" void kernel_launch(void* const* d_in, const int* in_sizes, int n_in,
                              void* d_out, int out_size)
{
    cudaFuncSetAttribute(gemmh<1,0>, cudaFuncAttributeMaxDynamicSharedMemorySize, GEMM_SMEM);
    cudaFuncSetAttribute(gemmh<1,1>, cudaFuncAttributeMaxDynamicSharedMemorySize, GEMM_SMEM);
    cudaFuncSetAttribute(gemmh<0,0>, cudaFuncAttributeMaxDynamicSharedMemorySize, GEMM_SMEM);

    float *px, *pt, *psc, *pb3;
    __half *pxh, *pqkv, *pct, *pvt, *psch, *pffh, *pwT;
    cudaGetSymbolAddress((void**)&px,   g_x);
    cudaGetSymbolAddress((void**)&pxh,  g_xh);
    cudaGetSymbolAddress((void**)&pqkv, g_qkv);
    cudaGetSymbolAddress((void**)&pct,  g_ct);
    cudaGetSymbolAddress((void**)&pt,   g_t);
    cudaGetSymbolAddress((void**)&pvt,  g_vt);
    cudaGetSymbolAddress((void**)&psc,  g_sc);
    cudaGetSymbolAddress((void**)&psch, g_sch);
    cudaGetSymbolAddress((void**)&pffh, g_ffh);
    cudaGetSymbolAddress((void**)&pwT,  g_wTh);
    cudaGetSymbolAddress((void**)&pb3,  g_b3);

    const int*   src = (const int*)  d_in[0];
    const float* emb = (const float*)d_in[2];
    const float* Wq  = (const float*)d_in[3];
    const float* bq  = (const float*)d_in[4];
    const float* Wk  = (const float*)d_in[5];
    const float* bk  = (const float*)d_in[6];
    const float* Wv  = (const float*)d_in[7];
    const float* bv  = (const float*)d_in[8];
    const float* Wo  = (const float*)d_in[9];
    const float* bo  = (const float*)d_in[10];
    const float* W1  = (const float*)d_in[11];
    const float* b1  = (const float*)d_in[12];
    const float* W2  = (const float*)d_in[13];
    const float* b2  = (const float*)d_in[14];
    const float* g1  = (const float*)d_in[15];
    const float* be1 = (const float*)d_in[16];
    const float* g2  = (const float*)d_in[17];
    const float* be2 = (const float*)d_in[18];
    const float* gf  = (const float*)d_in[19];
    const float* bf  = (const float*)d_in[20];
    float* out = (float*)d_out;

    // one-shot weight transposes -> fp16 [N][K]; Wq scaled by 1/32
    dim3 tb(32, 8);
    transpose_mat_h<<<dim3(HH/32,  HH/32,  LL), tb>>>(Wq, pwT + QKVT,            HH, HH, 3L*HH*HH, 1.0f/32.0f);
    transpose_mat_h<<<dim3(HH/32,  HH/32,  LL), tb>>>(Wk, pwT + QKVT + (long)HH*HH, HH, HH, 3L*HH*HH, 1.0f);
    transpose_mat_h<<<dim3(HH/32,  HH/32,  LL), tb>>>(Wv, pwT + QKVT + 2L*HH*HH, HH, HH, 3L*HH*HH, 1.0f);
    transpose_mat_h<<<dim3(HH/32,  HH/32,  LL), tb>>>(Wo, pwT + WOT, HH,  HH,  (long)HH*HH,  1.0f);
    transpose_mat_h<<<dim3(FFD/32, HH/32,  LL), tb>>>(W1, pwT + W1T, HH,  FFD, (long)HH*FFD, 1.0f);
    transpose_mat_h<<<dim3(HH/32,  FFD/32, LL), tb>>>(W2, pwT + W2T, FFD, HH,  (long)FFD*HH, 1.0f);
    pack_b3<<<(LL*3*HH + 255)/256, 256>>>(bq, bk, bv, pb3);

    embed_pe<<<MR, 256>>>(src, emb, px, pxh);

    const dim3 gQKV (3*HH / BN, MR / BM, 1);   // (24, 32)
    const dim3 gProj(HH / BN,   MR / BM, 1);   // (8, 32)
    const dim3 gFF1 (FFD / BN,  MR / BM, 1);   // (32, 32)
    const dim3 gAttn(SS / BN,   SS / BM, BB);  // (8, 4, 8)
    const dim3 gCtx (HH / BN,   SS / BM, BB);  // (8, 4, 8)

    for (int l = 0; l < LL; l++) {
        const __half* qkvT = pwT + QKVT + (long)l * 3 * HH * HH;
        const __half* woT  = pwT + WOT  + (long)l * HH * HH;
        const __half* w1T  = pwT + W1T  + (long)l * HH * FFD;
        const __half* w2T  = pwT + W2T  + (long)l * FFD * HH;
        const float* b3L = pb3 + (long)l * 3 * HH;
        const float* boL = bo + (long)l * HH;
        const float* b1L = b1 + (long)l * FFD;
        const float* b2L = b2 + (long)l * HH;
        const float* g1L = g1 + (long)l * HH;  const float* be1L = be1 + (long)l * HH;
        const float* g2L = g2 + (long)l * HH;  const float* be2L = be2 + (long)l * HH;

        // fused qkv = x @ [Wq/32|Wk|Wv]^T + [bq/32|bk|bv]   (fp16, packed rows)
        gemmh<1,0><<<gQKV, 256, GEMM_SMEM>>>(pxh, 0, HH, qkvT, 0, HH, b3L,
                                             pqkv, 0, 3*HH, HH, 1.0f);

        // vT[b][h][s]
        transpose_v_h<<<dim3(HH/32, SS/32, BB), tb>>>(pqkv, pvt);

        // scores[b] = Q_b @ K_b^T -> fp32
        gemmh<0,0><<<gAttn, 256, GEMM_SMEM>>>(pqkv,      3*HH, BB*3*HH,
                                              pqkv + HH, 3*HH, BB*3*HH, nullptr,
                                              psc, (long)SS*SS, SS, HH, 1.0f);
        softmax_rows<<<BB*SS, 256>>>(psc, psch);

        // ctx[b] = P_b @ V_b -> fp16 (S,B,H)
        gemmh<1,0><<<gCtx, 256, GEMM_SMEM>>>(psch, (long)SS*SS, SS,
                                             pvt, (long)HH*SS, SS, nullptr,
                                             pct, HH, BB*HH, SS, 1.0f);

        // src2 = ctx Wo + bo (fp32) ; x = LN(x + src2)
        gemmh<0,0><<<gProj, 256, GEMM_SMEM>>>(pct, 0, HH, woT, 0, HH, boL,
                                              pt, 0, HH, HH, 1.0f);
        add_ln<<<MR, 256>>>(px, pt, g1L, be1L, px, pxh);

        // ff = relu(x W1 + b1) fp16 ; ff2 = ff W2 + b2 fp32 ; x = LN(x + ff2)
        gemmh<1,1><<<gFF1, 256, GEMM_SMEM>>>(pxh, 0, HH, w1T, 0, HH, b1L,
                                             pffh, 0, FFD, HH, 1.0f);
        gemmh<0,0><<<gProj, 256, GEMM_SMEM>>>(pffh, 0, FFD, w2T, 0, FFD, b2L,
                                              pt, 0, HH, FFD, 1.0f);
        add_ln<<<MR, 256>>>(px, pt, g2L, be2L, px, pxh);
    }

    add_ln<<<MR, 256>>>(px, nullptr, gf, bf, out, nullptr);
}

// round 9
// speedup vs baseline: 1.1213x; 1.1213x over previous
#include <cuda_runtime.h>
#include <cuda_fp16.h>
#include <math.h>
#include <stdint.h>

// Problem constants
#define SS   1024
#define BB   8
#define HH   1024
#define LL   6
#define FFD  4096
#define MR   (SS*BB)

// ---------------------------------------------------------------------------
// Scratch (static device globals; no allocation anywhere)
// ---------------------------------------------------------------------------
__device__ float  g_x  [MR*HH];              // residual stream fp32
__device__ __half g_xh [MR*HH];              // fp16 copy of x
__device__ __half g_qkv[(long)MR*3*HH];      // packed q|k|v per row (fp16)
__device__ __half g_ct [MR*HH];              // ctx (fp16)
__device__ float  g_t  [MR*HH];              // residual branch fp32
__device__ __half g_vt [(long)BB*HH*SS];     // V transposed (B,H,S) fp16
__device__ float  g_sc [(long)BB*SS*SS];     // attention scores fp32
__device__ __half g_sch[(long)BB*SS*SS];     // softmax probs fp16
__device__ __half g_ffh[(long)MR*FFD];       // ff hidden fp16
__device__ __half g_wTh[75497472];           // transposed fp16 weights
__device__ float  g_b3 [LL*3*HH];            // packed qkv bias (bq/32|bk|bv)

// offsets (elements) inside g_wTh
#define QKVT 0L                                  // [L][3][H][H]
#define WOT  (18L*HH*HH)
#define W1T  (WOT + 6L*HH*HH)
#define W2T  (W1T + 6L*HH*FFD)

// ---------------------------------------------------------------------------
// fp16 tensor-core GEMM (mma.sync m16n8k16, fp32 accumulate, ldmatrix frags)
//   C[z] = (A[z] @ B[z]^T + bias) * alpha  (+ optional ReLU)
// A: M x K row-major fp16 (lda). B: N x K row-major fp16 (ldb).
// OUTH=1 -> C fp16 ; OUTH=0 -> C fp32.
// Block tile 128x128x64, 8 warps (warp 32x64), 2-stage cp.async double buffer.
// M,N multiples of 128; K multiple of 64.
// ---------------------------------------------------------------------------
__device__ __forceinline__ void mma16816(float* d, const uint32_t* a,
                                         uint32_t b0, uint32_t b1) {
    asm volatile(
        "mma.sync.aligned.m16n8k16.row.col.f32.f16.f16.f32 "
        "{%0,%1,%2,%3}, {%4,%5,%6,%7}, {%8,%9}, {%0,%1,%2,%3};"
        : "+f"(d[0]), "+f"(d[1]), "+f"(d[2]), "+f"(d[3])
        : "r"(a[0]), "r"(a[1]), "r"(a[2]), "r"(a[3]), "r"(b0), "r"(b1));
}
__device__ __forceinline__ void ldsm4(uint32_t* r, uint32_t addr) {
    asm volatile("ldmatrix.sync.aligned.m8n8.x4.shared.b16 {%0,%1,%2,%3}, [%4];"
                 : "=r"(r[0]), "=r"(r[1]), "=r"(r[2]), "=r"(r[3]) : "r"(addr));
}
__device__ __forceinline__ void cpa16(uint32_t dst, const void* src) {
    asm volatile("cp.async.cg.shared.global [%0], [%1], 16;" :: "r"(dst), "l"(src));
}
#define CP_COMMIT() asm volatile("cp.async.commit_group;" ::: "memory")
#define CP_WAIT(n)  asm volatile("cp.async.wait_group %0;" :: "n"(n) : "memory")

#define LDW     36                        // words/row (32 data + 4 pad); 36%32=4
#define STAGES  2
#define STG_W   (128 * LDW * 2)           // words per stage (A + B)
#define STG_B   (STG_W * 4u)              // bytes per stage
#define BOFF_B  (128u * LDW * 4u)         // B tile byte offset within stage
#define GEMM_SMEM (STAGES * STG_W * 4)    // 73728 bytes

template<int OUTH, int RELU>
__global__ void __launch_bounds__(256, 2)
gemmh(const __half* __restrict__ A, long sA, int lda,
      const __half* __restrict__ B, long sB, int ldb,
      const float* __restrict__ bias,
      void* __restrict__ Cv, long sC, int ldc,
      int K, float alpha)
{
    extern __shared__ __align__(16) uint32_t sm[];
    const uint32_t sbase = (uint32_t)__cvta_generic_to_shared(sm);

    A += (long)blockIdx.z * sA;
    B += (long)blockIdx.z * sB;
    __half* Ch = (__half*)Cv + (OUTH ? (long)blockIdx.z * sC : 0);
    float*  Cf = (float*) Cv + (OUTH ? 0 : (long)blockIdx.z * sC);

    const int bm = blockIdx.y * 128, bn = blockIdx.x * 128;
    const int tid = threadIdx.x;
    const int wid = tid >> 5, lane = tid & 31;
    const int wm = (wid >> 1) * 32, wn = (wid & 1) * 64;
    const int r = lane >> 2, c = lane & 3;

    float acc[2][8][4];
    #pragma unroll
    for (int im = 0; im < 2; im++)
        #pragma unroll
        for (int jn = 0; jn < 8; jn++)
            #pragma unroll
            for (int q = 0; q < 4; q++) acc[im][jn][q] = 0.f;

    // cp.async staging: 2 threads/row; thread handles 4 x 16B chunks
    // chunk j: global halfs [j*8, j*8+8), smem words [j*4, j*4+4)
    const int crow = tid >> 1;
    const int cch  = (tid & 1) * 4;                 // chunks cch..cch+3 of 8
    const __half* Arow = A + (long)(bm + crow) * lda;
    const __half* Brow = B + (long)(bn + crow) * ldb;
    const uint32_t adst = sbase + (uint32_t)(crow * LDW + cch * 4) * 4u;
    const uint32_t bdst = sbase + BOFF_B + (uint32_t)(crow * LDW + cch * 4) * 4u;

    auto issue = [&](int t) {
        const uint32_t so = (uint32_t)(t % STAGES) * STG_B;
        const long k0 = (long)t * 64;
        #pragma unroll
        for (int j = 0; j < 4; j++) {
            cpa16(adst + so + (uint32_t)j * 16u, Arow + k0 + (cch + j) * 8);
            cpa16(bdst + so + (uint32_t)j * 16u, Brow + k0 + (cch + j) * 8);
        }
        CP_COMMIT();
    };

    // ldmatrix base addresses (validated lane maps, pitch now LDW=36):
    // A x4 (16x16): lanes 0-15 -> row wm+(lane&15); lanes 16-31 -> +16B k-chunk
    const uint32_t aAddr = sbase
        + (uint32_t)((wm + (lane & 15)) * LDW) * 4u + (uint32_t)(lane >> 4) * 16u;
    // B x4 (two 8-row n-tiles x two k-chunks)
    const uint32_t bAddr = sbase + BOFF_B
        + (uint32_t)((wn + (lane & 7) + ((lane >> 4) << 3)) * LDW) * 4u
        + (uint32_t)((lane >> 3) & 1) * 16u;

    const int nt = K / 64;
    issue(0);

    for (int t = 0; t < nt; t++) {
        CP_WAIT(0);
        __syncthreads();
        if (t + 1 < nt) issue(t + 1);

        const uint32_t so = (uint32_t)(t % STAGES) * STG_B;
        #pragma unroll
        for (int ks = 0; ks < 4; ks++) {
            const uint32_t ko = so + (uint32_t)ks * 32u;   // ks*8 words
            uint32_t a0[4], a1[4];
            ldsm4(a0, aAddr + ko);
            ldsm4(a1, aAddr + ko + 16u * LDW * 4u);
            #pragma unroll
            for (int jp = 0; jp < 4; jp++) {
                uint32_t b[4];
                ldsm4(b, bAddr + ko + (uint32_t)jp * (16u * LDW * 4u));
                mma16816(acc[0][2*jp    ], a0, b[0], b[1]);
                mma16816(acc[0][2*jp + 1], a0, b[2], b[3]);
                mma16816(acc[1][2*jp    ], a1, b[0], b[1]);
                mma16816(acc[1][2*jp + 1], a1, b[2], b[3]);
            }
        }
        __syncthreads();
    }

    // epilogue: bias -> alpha -> relu
    #pragma unroll
    for (int im = 0; im < 2; im++) {
        #pragma unroll
        for (int jn = 0; jn < 8; jn++) {
            int m = bm + wm + im * 16 + r;
            int n = bn + wn + jn * 8 + 2 * c;
            float v0 = acc[im][jn][0], v1 = acc[im][jn][1];
            float v2 = acc[im][jn][2], v3 = acc[im][jn][3];
            if (bias) {
                float bb0 = bias[n], bb1 = bias[n + 1];
                v0 += bb0; v1 += bb1; v2 += bb0; v3 += bb1;
            }
            v0 *= alpha; v1 *= alpha; v2 *= alpha; v3 *= alpha;
            if (RELU) {
                v0 = fmaxf(v0, 0.f); v1 = fmaxf(v1, 0.f);
                v2 = fmaxf(v2, 0.f); v3 = fmaxf(v3, 0.f);
            }
            if (OUTH) {
                *(__half2*)&Ch[(long)m * ldc + n] = __floats2half2_rn(v0, v1);
                *(__half2*)&Ch[(long)(m + 8) * ldc + n] = __floats2half2_rn(v2, v3);
            } else {
                *(float2*)&Cf[(long)m * ldc + n] = make_float2(v0, v1);
                *(float2*)&Cf[(long)(m + 8) * ldc + n] = make_float2(v2, v3);
            }
        }
    }
}

// ---------------------------------------------------------------------------
// Transposes / packing
// ---------------------------------------------------------------------------
__global__ void transpose_mat_h(const float* __restrict__ src, __half* __restrict__ dst,
                                int R, int C, long zdst, float scale) {
    __shared__ float t[32][33];
    long z = blockIdx.z;
    src += z * (long)R * C;
    dst += z * zdst;
    int r0 = blockIdx.y * 32, c0 = blockIdx.x * 32;
    int x = threadIdx.x, y = threadIdx.y;
    #pragma unroll
    for (int i = 0; i < 32; i += 8)
        t[y + i][x] = src[(long)(r0 + y + i) * C + c0 + x];
    __syncthreads();
    #pragma unroll
    for (int i = 0; i < 32; i += 8)
        dst[(long)(c0 + y + i) * R + r0 + x] = __float2half_rn(t[x][y + i] * scale);
}

__global__ void pack_b3(const float* __restrict__ bq, const float* __restrict__ bk,
                        const float* __restrict__ bv, float* __restrict__ b3) {
    int i = blockIdx.x * 256 + threadIdx.x;
    if (i >= LL * 3 * HH) return;
    int l = i / (3 * HH), j = i % (3 * HH);
    float v;
    if (j < HH)          v = bq[l * HH + j] * (1.0f / 32.0f);
    else if (j < 2 * HH) v = bk[l * HH + j - HH];
    else                 v = bv[l * HH + j - 2 * HH];
    b3[i] = v;
}

// vT[b][h][s] = qkv[(s*B+b)*3H + 2H + h]
__global__ void transpose_v_h(const __half* __restrict__ qkv, __half* __restrict__ vt) {
    __shared__ __half t[32][34];
    int b = blockIdx.z;
    int s0 = blockIdx.y * 32, h0 = blockIdx.x * 32;
    int x = threadIdx.x, y = threadIdx.y;
    #pragma unroll
    for (int i = 0; i < 32; i += 8)
        t[y + i][x] = qkv[((long)(s0 + y + i) * BB + b) * 3 * HH + 2 * HH + h0 + x];
    __syncthreads();
    #pragma unroll
    for (int i = 0; i < 32; i += 8)
        vt[((long)b * HH + h0 + y + i) * SS + s0 + x] = t[x][y + i];
}

// ---------------------------------------------------------------------------
// Embedding + positional encoding (fp32 + fp16)
// ---------------------------------------------------------------------------
__global__ void embed_pe(const int* __restrict__ src,
                         const float* __restrict__ emb,
                         float* __restrict__ x, __half* __restrict__ xh) {
    int row = blockIdx.x;
    int s = row / BB;
    int tok = src[row];
    const float cc = -logf(10000.0f) / (float)HH;
    for (int h = threadIdx.x; h < HH; h += blockDim.x) {
        int i2 = (h >> 1) << 1;
        float div = expf(cc * (float)i2);
        float ang = (float)s * div;
        float pe = (h & 1) ? cosf(ang) : sinf(ang);
        float u = emb[(long)tok * HH + h] * 32.0f + pe;
        x [(long)row * HH + h] = u;
        xh[(long)row * HH + h] = __float2half_rn(u);
    }
}

// ---------------------------------------------------------------------------
// Reductions + softmax + add&LayerNorm
// ---------------------------------------------------------------------------
__device__ __forceinline__ float warpSum(float v) {
    #pragma unroll
    for (int o = 16; o; o >>= 1) v += __shfl_xor_sync(0xffffffffu, v, o);
    return v;
}
__device__ __forceinline__ float warpMax(float v) {
    #pragma unroll
    for (int o = 16; o; o >>= 1) v = fmaxf(v, __shfl_xor_sync(0xffffffffu, v, o));
    return v;
}
__device__ float blockSum(float v) {
    __shared__ float s[8];
    int lane = threadIdx.x & 31, w = threadIdx.x >> 5;
    v = warpSum(v);
    if (!lane) s[w] = v;
    __syncthreads();
    float r;
    if (w == 0) {
        float t = (lane < 8) ? s[lane] : 0.f;
        #pragma unroll
        for (int o = 4; o; o >>= 1) t += __shfl_xor_sync(0xffffffffu, t, o);
        if (!lane) s[0] = t;
    }
    __syncthreads();
    r = s[0];
    __syncthreads();
    return r;
}
__device__ float blockMax(float v) {
    __shared__ float s[8];
    int lane = threadIdx.x & 31, w = threadIdx.x >> 5;
    v = warpMax(v);
    if (!lane) s[w] = v;
    __syncthreads();
    float r;
    if (w == 0) {
        float t = (lane < 8) ? s[lane] : -3.0e38f;
        #pragma unroll
        for (int o = 4; o; o >>= 1) t = fmaxf(t, __shfl_xor_sync(0xffffffffu, t, o));
        if (!lane) s[0] = t;
    }
    __syncthreads();
    r = s[0];
    __syncthreads();
    return r;
}

__global__ void softmax_rows(const float* __restrict__ sc, __half* __restrict__ ph) {
    long row = blockIdx.x;
    const float* p = sc + row * SS;
    __half* o = ph + row * SS;
    int t = threadIdx.x;
    float v[4];
    float mx = -3.0e38f;
    #pragma unroll
    for (int j = 0; j < 4; j++) { v[j] = p[t + j * 256]; mx = fmaxf(mx, v[j]); }
    mx = blockMax(mx);
    float sum = 0.f;
    #pragma unroll
    for (int j = 0; j < 4; j++) { v[j] = expf(v[j] - mx); sum += v[j]; }
    sum = blockSum(sum);
    float inv = 1.0f / sum;
    #pragma unroll
    for (int j = 0; j < 4; j++) o[t + j * 256] = __float2half_rn(v[j] * inv);
}

__global__ void add_ln(const float* __restrict__ x, const float* __restrict__ y,
                       const float* __restrict__ g, const float* __restrict__ b,
                       float* __restrict__ out, __half* __restrict__ outh) {
    long row = blockIdx.x;
    const float* px = x + row * HH;
    const float* py = y ? y + row * HH : nullptr;
    int t = threadIdx.x;
    float v[4];
    float sum = 0.f;
    #pragma unroll
    for (int j = 0; j < 4; j++) {
        float u = px[t + j * 256];
        if (py) u += py[t + j * 256];
        v[j] = u; sum += u;
    }
    sum = blockSum(sum);
    float m = sum * (1.0f / HH);
    float ss = 0.f;
    #pragma unroll
    for (int j = 0; j < 4; j++) { float d = v[j] - m; ss += d * d; }
    ss = blockSum(ss);
    float inv = rsqrtf(ss * (1.0f / HH) + 1e-5f);
    #pragma unroll
    for (int j = 0; j < 4; j++) {
        int h = t + j * 256;
        float o = (v[j] - m) * inv * g[h] + b[h];
        out[row * HH + h] = o;
        if (outh) outh[row * HH + h] = __float2half_rn(o);
    }
}

// ---------------------------------------------------------------------------
// Launcher
// ---------------------------------------------------------------------------
extern "C" void kernel_launch(void* const* d_in, const int* in_sizes, int n_in,
                              void* d_out, int out_size)
{
    cudaFuncSetAttribute(gemmh<1,0>, cudaFuncAttributeMaxDynamicSharedMemorySize, GEMM_SMEM);
    cudaFuncSetAttribute(gemmh<1,1>, cudaFuncAttributeMaxDynamicSharedMemorySize, GEMM_SMEM);
    cudaFuncSetAttribute(gemmh<0,0>, cudaFuncAttributeMaxDynamicSharedMemorySize, GEMM_SMEM);

    float *px, *pt, *psc, *pb3;
    __half *pxh, *pqkv, *pct, *pvt, *psch, *pffh, *pwT;
    cudaGetSymbolAddress((void**)&px,   g_x);
    cudaGetSymbolAddress((void**)&pxh,  g_xh);
    cudaGetSymbolAddress((void**)&pqkv, g_qkv);
    cudaGetSymbolAddress((void**)&pct,  g_ct);
    cudaGetSymbolAddress((void**)&pt,   g_t);
    cudaGetSymbolAddress((void**)&pvt,  g_vt);
    cudaGetSymbolAddress((void**)&psc,  g_sc);
    cudaGetSymbolAddress((void**)&psch, g_sch);
    cudaGetSymbolAddress((void**)&pffh, g_ffh);
    cudaGetSymbolAddress((void**)&pwT,  g_wTh);
    cudaGetSymbolAddress((void**)&pb3,  g_b3);

    const int*   src = (const int*)  d_in[0];
    const float* emb = (const float*)d_in[2];
    const float* Wq  = (const float*)d_in[3];
    const float* bq  = (const float*)d_in[4];
    const float* Wk  = (const float*)d_in[5];
    const float* bk  = (const float*)d_in[6];
    const float* Wv  = (const float*)d_in[7];
    const float* bv  = (const float*)d_in[8];
    const float* Wo  = (const float*)d_in[9];
    const float* bo  = (const float*)d_in[10];
    const float* W1  = (const float*)d_in[11];
    const float* b1  = (const float*)d_in[12];
    const float* W2  = (const float*)d_in[13];
    const float* b2  = (const float*)d_in[14];
    const float* g1  = (const float*)d_in[15];
    const float* be1 = (const float*)d_in[16];
    const float* g2  = (const float*)d_in[17];
    const float* be2 = (const float*)d_in[18];
    const float* gf  = (const float*)d_in[19];
    const float* bf  = (const float*)d_in[20];
    float* out = (float*)d_out;

    // one-shot weight transposes -> fp16 [N][K]; Wq scaled by 1/32
    dim3 tb(32, 8);
    transpose_mat_h<<<dim3(HH/32,  HH/32,  LL), tb>>>(Wq, pwT + QKVT,            HH, HH, 3L*HH*HH, 1.0f/32.0f);
    transpose_mat_h<<<dim3(HH/32,  HH/32,  LL), tb>>>(Wk, pwT + QKVT + (long)HH*HH, HH, HH, 3L*HH*HH, 1.0f);
    transpose_mat_h<<<dim3(HH/32,  HH/32,  LL), tb>>>(Wv, pwT + QKVT + 2L*HH*HH, HH, HH, 3L*HH*HH, 1.0f);
    transpose_mat_h<<<dim3(HH/32,  HH/32,  LL), tb>>>(Wo, pwT + WOT, HH,  HH,  (long)HH*HH,  1.0f);
    transpose_mat_h<<<dim3(FFD/32, HH/32,  LL), tb>>>(W1, pwT + W1T, HH,  FFD, (long)HH*FFD, 1.0f);
    transpose_mat_h<<<dim3(HH/32,  FFD/32, LL), tb>>>(W2, pwT + W2T, FFD, HH,  (long)FFD*HH, 1.0f);
    pack_b3<<<(LL*3*HH + 255)/256, 256>>>(bq, bk, bv, pb3);

    embed_pe<<<MR, 256>>>(src, emb, px, pxh);

    const dim3 gQKV (3*HH / 128, MR / 128, 1);  // (24, 64)
    const dim3 gProj(HH / 128,   MR / 128, 1);  // (8, 64)
    const dim3 gFF1 (FFD / 128,  MR / 128, 1);  // (32, 64)
    const dim3 gAttn(SS / 128,   SS / 128, BB); // (8, 8, 8)
    const dim3 gCtx (HH / 128,   SS / 128, BB); // (8, 8, 8)

    for (int l = 0; l < LL; l++) {
        const __half* qkvT = pwT + QKVT + (long)l * 3 * HH * HH;
        const __half* woT  = pwT + WOT  + (long)l * HH * HH;
        const __half* w1T  = pwT + W1T  + (long)l * HH * FFD;
        const __half* w2T  = pwT + W2T  + (long)l * FFD * HH;
        const float* b3L = pb3 + (long)l * 3 * HH;
        const float* boL = bo + (long)l * HH;
        const float* b1L = b1 + (long)l * FFD;
        const float* b2L = b2 + (long)l * HH;
        const float* g1L = g1 + (long)l * HH;  const float* be1L = be1 + (long)l * HH;
        const float* g2L = g2 + (long)l * HH;  const float* be2L = be2 + (long)l * HH;

        // fused qkv = x @ [Wq/32|Wk|Wv]^T + [bq/32|bk|bv]   (fp16, packed rows)
        gemmh<1,0><<<gQKV, 256, GEMM_SMEM>>>(pxh, 0, HH, qkvT, 0, HH, b3L,
                                             pqkv, 0, 3*HH, HH, 1.0f);

        // vT[b][h][s]
        transpose_v_h<<<dim3(HH/32, SS/32, BB), tb>>>(pqkv, pvt);

        // scores[b] = Q_b @ K_b^T -> fp32
        gemmh<0,0><<<gAttn, 256, GEMM_SMEM>>>(pqkv,      3*HH, BB*3*HH,
                                              pqkv + HH, 3*HH, BB*3*HH, nullptr,
                                              psc, (long)SS*SS, SS, HH, 1.0f);
        softmax_rows<<<BB*SS, 256>>>(psc, psch);

        // ctx[b] = P_b @ V_b -> fp16 (S,B,H)
        gemmh<1,0><<<gCtx, 256, GEMM_SMEM>>>(psch, (long)SS*SS, SS,
                                             pvt, (long)HH*SS, SS, nullptr,
                                             pct, HH, BB*HH, SS, 1.0f);

        // src2 = ctx Wo + bo (fp32) ; x = LN(x + src2)
        gemmh<0,0><<<gProj, 256, GEMM_SMEM>>>(pct, 0, HH, woT, 0, HH, boL,
                                              pt, 0, HH, HH, 1.0f);
        add_ln<<<MR, 256>>>(px, pt, g1L, be1L, px, pxh);

        // ff = relu(x W1 + b1) fp16 ; ff2 = ff W2 + b2 fp32 ; x = LN(x + ff2)
        gemmh<1,1><<<gFF1, 256, GEMM_SMEM>>>(pxh, 0, HH, w1T, 0, HH, b1L,
                                             pffh, 0, FFD, HH, 1.0f);
        gemmh<0,0><<<gProj, 256, GEMM_SMEM>>>(pffh, 0, FFD, w2T, 0, FFD, b2L,
                                              pt, 0, HH, FFD, 1.0f);
        add_ln<<<MR, 256>>>(px, pt, g2L, be2L, px, pxh);
    }

    add_ln<<<MR, 256>>>(px, nullptr, gf, bf, out, nullptr);
}

// round 10
// speedup vs baseline: 1.2502x; 1.1150x over previous
#include <cuda_runtime.h>
#include <cuda_fp16.h>
#include <math.h>
#include <stdint.h>

// Problem constants
#define SS   1024
#define BB   8
#define HH   1024
#define LL   6
#define FFD  4096
#define MR   (SS*BB)

// ---------------------------------------------------------------------------
// Scratch (static device globals; no allocation anywhere)
// ---------------------------------------------------------------------------
__device__ float  g_x  [MR*HH];              // residual stream fp32
__device__ __half g_xh [MR*HH];              // fp16 copy of x
__device__ __half g_qkv[(long)MR*3*HH];      // packed q|k|v per row (fp16)
__device__ __half g_ct [MR*HH];              // ctx (fp16)
__device__ float  g_t  [MR*HH];              // residual branch fp32
__device__ __half g_vt [(long)BB*HH*SS];     // V transposed (B,H,S) fp16
__device__ __half g_sch[(long)BB*SS*SS];     // unnormalized probs exp(s-4) fp16
__device__ float  g_rs [BB*SS];              // 1 / row sums
__device__ __half g_ffh[(long)MR*FFD];       // ff hidden fp16
__device__ __half g_wTh[75497472];           // transposed fp16 weights
__device__ float  g_b3 [LL*3*HH];            // packed qkv bias (bq/32|bk|bv)

// offsets (elements) inside g_wTh
#define QKVT 0L                                  // [L][3][H][H]
#define WOT  (18L*HH*HH)
#define W1T  (WOT + 6L*HH*HH)
#define W2T  (W1T + 6L*HH*FFD)

// ---------------------------------------------------------------------------
// fp16 tensor-core GEMM (mma.sync m16n8k16, fp32 accumulate, ldmatrix frags)
//   acc = A[z] @ B[z]^T ;  epilogue by MODE:
//     0: fp32 out, +bias, *alpha
//     1: fp16 out, +bias, *alpha
//     2: fp16 out, +bias, *alpha, relu
//     3: fp16 out, exp(acc - 4)                  (scores -> unnormalized probs)
//     4: fp16 out, acc * rsc[m]                  (ctx, row-scaled by 1/rowsum)
// A: M x K row-major fp16 (lda). B: N x K row-major fp16 (ldb).
// Block tile 128x128x32, 8 warps (32x64), 5-stage cp.async ring. (round-7 core)
// ---------------------------------------------------------------------------
__device__ __forceinline__ void mma16816(float* d, const uint32_t* a,
                                         uint32_t b0, uint32_t b1) {
    asm volatile(
        "mma.sync.aligned.m16n8k16.row.col.f32.f16.f16.f32 "
        "{%0,%1,%2,%3}, {%4,%5,%6,%7}, {%8,%9}, {%0,%1,%2,%3};"
        : "+f"(d[0]), "+f"(d[1]), "+f"(d[2]), "+f"(d[3])
        : "r"(a[0]), "r"(a[1]), "r"(a[2]), "r"(a[3]), "r"(b0), "r"(b1));
}
__device__ __forceinline__ void ldsm4(uint32_t* r, uint32_t addr) {
    asm volatile("ldmatrix.sync.aligned.m8n8.x4.shared.b16 {%0,%1,%2,%3}, [%4];"
                 : "=r"(r[0]), "=r"(r[1]), "=r"(r[2]), "=r"(r[3]) : "r"(addr));
}
__device__ __forceinline__ void cpa16(uint32_t dst, const void* src) {
    asm volatile("cp.async.cg.shared.global [%0], [%1], 16;" :: "r"(dst), "l"(src));
}
#define CP_COMMIT() asm volatile("cp.async.commit_group;" ::: "memory")
#define CP_WAIT(n)  asm volatile("cp.async.wait_group %0;" :: "n"(n) : "memory")

#define LDW     20                        // uint32 words/row (16 data + 4 pad)
#define STAGES  5
#define STG_W   (128 * LDW * 2)           // words per stage (A + B)
#define STG_B   (STG_W * 4u)              // bytes per stage
#define BOFF_B  (128u * LDW * 4u)         // B tile byte offset within stage
#define GEMM_SMEM (STAGES * STG_W * 4)    // 102400 bytes

template<int MODE>
__global__ void __launch_bounds__(256, 2)
gemmh(const __half* __restrict__ A, long sA, int lda,
      const __half* __restrict__ B, long sB, int ldb,
      const float* __restrict__ bias,
      const float* __restrict__ rsc, long sR,
      void* __restrict__ Cv, long sC, int ldc,
      int K, float alpha)
{
    extern __shared__ __align__(16) uint32_t sm[];
    const uint32_t sbase = (uint32_t)__cvta_generic_to_shared(sm);

    A += (long)blockIdx.z * sA;
    B += (long)blockIdx.z * sB;
    if (MODE == 4) rsc += (long)blockIdx.z * sR;
    __half* Ch = (__half*)Cv + (MODE != 0 ? (long)blockIdx.z * sC : 0);
    float*  Cf = (float*) Cv + (MODE == 0 ? (long)blockIdx.z * sC : 0);

    const int bm = blockIdx.y * 128, bn = blockIdx.x * 128;
    const int tid = threadIdx.x;
    const int wid = tid >> 5, lane = tid & 31;
    const int wm = (wid >> 1) * 32, wn = (wid & 1) * 64;
    const int r = lane >> 2, c = lane & 3;

    float acc[2][8][4];
    #pragma unroll
    for (int im = 0; im < 2; im++)
        #pragma unroll
        for (int jn = 0; jn < 8; jn++)
            #pragma unroll
            for (int q = 0; q < 4; q++) acc[im][jn][q] = 0.f;

    // cp.async staging: thread -> row crow, 16B chunks cch, cch+1
    const int crow = tid >> 1;
    const int cch  = (tid & 1) * 2;
    const __half* Arow = A + (long)(bm + crow) * lda;
    const __half* Brow = B + (long)(bn + crow) * ldb;
    const uint32_t adst = sbase + (uint32_t)(crow * LDW + cch * 4) * 4u;
    const uint32_t bdst = adst + BOFF_B;

    auto issue = [&](int t) {
        const uint32_t so = (uint32_t)(t % STAGES) * STG_B;
        const long k0 = (long)t * 32;
        cpa16(adst + so,       Arow + k0 + cch * 8);
        cpa16(adst + so + 16u, Arow + k0 + (cch + 1) * 8);
        cpa16(bdst + so,       Brow + k0 + cch * 8);
        cpa16(bdst + so + 16u, Brow + k0 + (cch + 1) * 8);
        CP_COMMIT();
    };

    // ldmatrix base addresses (validated round-7 lane maps):
    const uint32_t aAddr = sbase
        + (uint32_t)((wm + (lane & 15)) * LDW) * 4u + (uint32_t)(lane >> 4) * 16u;
    const uint32_t bAddr = sbase + BOFF_B
        + (uint32_t)((wn + (lane & 7) + ((lane >> 4) << 3)) * LDW) * 4u
        + (uint32_t)((lane >> 3) & 1) * 16u;

    const int nt = K / 32;
    #pragma unroll
    for (int t = 0; t < STAGES - 1; t++) {
        if (t < nt) issue(t); else CP_COMMIT();
    }

    for (int t = 0; t < nt; t++) {
        CP_WAIT(STAGES - 2);
        __syncthreads();
        if (t + STAGES - 1 < nt) issue(t + STAGES - 1);
        else CP_COMMIT();

        const uint32_t so = (uint32_t)(t % STAGES) * STG_B;
        #pragma unroll
        for (int ks = 0; ks < 2; ks++) {
            const uint32_t ko = so + (uint32_t)ks * 32u;   // ks*8 words
            uint32_t a0[4], a1[4];
            ldsm4(a0, aAddr + ko);
            ldsm4(a1, aAddr + ko + 16u * LDW * 4u);
            #pragma unroll
            for (int jp = 0; jp < 4; jp++) {
                uint32_t b[4];
                ldsm4(b, bAddr + ko + (uint32_t)jp * (16u * LDW * 4u));
                mma16816(acc[0][2*jp    ], a0, b[0], b[1]);
                mma16816(acc[0][2*jp + 1], a0, b[2], b[3]);
                mma16816(acc[1][2*jp    ], a1, b[0], b[1]);
                mma16816(acc[1][2*jp + 1], a1, b[2], b[3]);
            }
        }
    }

    // epilogue
    #pragma unroll
    for (int im = 0; im < 2; im++) {
        #pragma unroll
        for (int jn = 0; jn < 8; jn++) {
            int m = bm + wm + im * 16 + r;
            int n = bn + wn + jn * 8 + 2 * c;
            float v0 = acc[im][jn][0], v1 = acc[im][jn][1];
            float v2 = acc[im][jn][2], v3 = acc[im][jn][3];
            if (MODE <= 2) {
                if (bias) {
                    float bb0 = bias[n], bb1 = bias[n + 1];
                    v0 += bb0; v1 += bb1; v2 += bb0; v3 += bb1;
                }
                v0 *= alpha; v1 *= alpha; v2 *= alpha; v3 *= alpha;
            }
            if (MODE == 2) {
                v0 = fmaxf(v0, 0.f); v1 = fmaxf(v1, 0.f);
                v2 = fmaxf(v2, 0.f); v3 = fmaxf(v3, 0.f);
            }
            if (MODE == 3) {
                v0 = expf(v0 - 4.0f); v1 = expf(v1 - 4.0f);
                v2 = expf(v2 - 4.0f); v3 = expf(v3 - 4.0f);
            }
            if (MODE == 4) {
                float s0 = rsc[m], s8 = rsc[m + 8];
                v0 *= s0; v1 *= s0; v2 *= s8; v3 *= s8;
            }
            if (MODE != 0) {
                *(__half2*)&Ch[(long)m * ldc + n] = __floats2half2_rn(v0, v1);
                *(__half2*)&Ch[(long)(m + 8) * ldc + n] = __floats2half2_rn(v2, v3);
            } else {
                *(float2*)&Cf[(long)m * ldc + n] = make_float2(v0, v1);
                *(float2*)&Cf[(long)(m + 8) * ldc + n] = make_float2(v2, v3);
            }
        }
    }
}

// ---------------------------------------------------------------------------
// Transposes / packing
// ---------------------------------------------------------------------------
__global__ void transpose_mat_h(const float* __restrict__ src, __half* __restrict__ dst,
                                int R, int C, long zdst, float scale) {
    __shared__ float t[32][33];
    long z = blockIdx.z;
    src += z * (long)R * C;
    dst += z * zdst;
    int r0 = blockIdx.y * 32, c0 = blockIdx.x * 32;
    int x = threadIdx.x, y = threadIdx.y;
    #pragma unroll
    for (int i = 0; i < 32; i += 8)
        t[y + i][x] = src[(long)(r0 + y + i) * C + c0 + x];
    __syncthreads();
    #pragma unroll
    for (int i = 0; i < 32; i += 8)
        dst[(long)(c0 + y + i) * R + r0 + x] = __float2half_rn(t[x][y + i] * scale);
}

__global__ void pack_b3(const float* __restrict__ bq, const float* __restrict__ bk,
                        const float* __restrict__ bv, float* __restrict__ b3) {
    int i = blockIdx.x * 256 + threadIdx.x;
    if (i >= LL * 3 * HH) return;
    int l = i / (3 * HH), j = i % (3 * HH);
    float v;
    if (j < HH)          v = bq[l * HH + j] * (1.0f / 32.0f);
    else if (j < 2 * HH) v = bk[l * HH + j - HH];
    else                 v = bv[l * HH + j - 2 * HH];
    b3[i] = v;
}

// vT[b][h][s] = qkv[(s*B+b)*3H + 2H + h]
__global__ void transpose_v_h(const __half* __restrict__ qkv, __half* __restrict__ vt) {
    __shared__ __half t[32][34];
    int b = blockIdx.z;
    int s0 = blockIdx.y * 32, h0 = blockIdx.x * 32;
    int x = threadIdx.x, y = threadIdx.y;
    #pragma unroll
    for (int i = 0; i < 32; i += 8)
        t[y + i][x] = qkv[((long)(s0 + y + i) * BB + b) * 3 * HH + 2 * HH + h0 + x];
    __syncthreads();
    #pragma unroll
    for (int i = 0; i < 32; i += 8)
        vt[((long)b * HH + h0 + y + i) * SS + s0 + x] = t[x][y + i];
}

// ---------------------------------------------------------------------------
// Embedding + positional encoding (fp32 + fp16)
// ---------------------------------------------------------------------------
__global__ void embed_pe(const int* __restrict__ src,
                         const float* __restrict__ emb,
                         float* __restrict__ x, __half* __restrict__ xh) {
    int row = blockIdx.x;
    int s = row / BB;
    int tok = src[row];
    const float cc = -logf(10000.0f) / (float)HH;
    for (int h = threadIdx.x; h < HH; h += blockDim.x) {
        int i2 = (h >> 1) << 1;
        float div = expf(cc * (float)i2);
        float ang = (float)s * div;
        float pe = (h & 1) ? cosf(ang) : sinf(ang);
        float u = emb[(long)tok * HH + h] * 32.0f + pe;
        x [(long)row * HH + h] = u;
        xh[(long)row * HH + h] = __float2half_rn(u);
    }
}

// ---------------------------------------------------------------------------
// Reductions + rowsum + add&LayerNorm
// ---------------------------------------------------------------------------
__device__ __forceinline__ float warpSum(float v) {
    #pragma unroll
    for (int o = 16; o; o >>= 1) v += __shfl_xor_sync(0xffffffffu, v, o);
    return v;
}
__device__ float blockSum(float v) {
    __shared__ float s[8];
    int lane = threadIdx.x & 31, w = threadIdx.x >> 5;
    v = warpSum(v);
    if (!lane) s[w] = v;
    __syncthreads();
    float r;
    if (w == 0) {
        float t = (lane < 8) ? s[lane] : 0.f;
        #pragma unroll
        for (int o = 4; o; o >>= 1) t += __shfl_xor_sync(0xffffffffu, t, o);
        if (!lane) s[0] = t;
    }
    __syncthreads();
    r = s[0];
    __syncthreads();
    return r;
}

// rsinv[row] = 1 / sum(probs[row, :])
__global__ void rowsum_inv(const __half* __restrict__ ph, float* __restrict__ rsinv) {
    long row = blockIdx.x;                       // b*S + q
    const __half2* p = (const __half2*)(ph + row * SS);
    int t = threadIdx.x;                         // 256 threads, 2 half2 each
    float s = 0.f;
    #pragma unroll
    for (int j = 0; j < 2; j++) {
        float2 u = __half22float2(p[t + j * 256]);
        s += u.x + u.y;
    }
    s = blockSum(s);
    if (t == 0) rsinv[row] = 1.0f / s;
}

__global__ void add_ln(const float* __restrict__ x, const float* __restrict__ y,
                       const float* __restrict__ g, const float* __restrict__ b,
                       float* __restrict__ out, __half* __restrict__ outh) {
    long row = blockIdx.x;
    const float* px = x + row * HH;
    const float* py = y ? y + row * HH : nullptr;
    int t = threadIdx.x;
    float v[4];
    float sum = 0.f;
    #pragma unroll
    for (int j = 0; j < 4; j++) {
        float u = px[t + j * 256];
        if (py) u += py[t + j * 256];
        v[j] = u; sum += u;
    }
    sum = blockSum(sum);
    float m = sum * (1.0f / HH);
    float ss = 0.f;
    #pragma unroll
    for (int j = 0; j < 4; j++) { float d = v[j] - m; ss += d * d; }
    ss = blockSum(ss);
    float inv = rsqrtf(ss * (1.0f / HH) + 1e-5f);
    #pragma unroll
    for (int j = 0; j < 4; j++) {
        int h = t + j * 256;
        float o = (v[j] - m) * inv * g[h] + b[h];
        out[row * HH + h] = o;
        if (outh) outh[row * HH + h] = __float2half_rn(o);
    }
}

// ---------------------------------------------------------------------------
// Launcher
// ---------------------------------------------------------------------------
extern "C" void kernel_launch(void* const* d_in, const int* in_sizes, int n_in,
                              void* d_out, int out_size)
{
    cudaFuncSetAttribute(gemmh<0>, cudaFuncAttributeMaxDynamicSharedMemorySize, GEMM_SMEM);
    cudaFuncSetAttribute(gemmh<1>, cudaFuncAttributeMaxDynamicSharedMemorySize, GEMM_SMEM);
    cudaFuncSetAttribute(gemmh<2>, cudaFuncAttributeMaxDynamicSharedMemorySize, GEMM_SMEM);
    cudaFuncSetAttribute(gemmh<3>, cudaFuncAttributeMaxDynamicSharedMemorySize, GEMM_SMEM);
    cudaFuncSetAttribute(gemmh<4>, cudaFuncAttributeMaxDynamicSharedMemorySize, GEMM_SMEM);

    float *px, *pt, *prs, *pb3;
    __half *pxh, *pqkv, *pct, *pvt, *psch, *pffh, *pwT;
    cudaGetSymbolAddress((void**)&px,   g_x);
    cudaGetSymbolAddress((void**)&pxh,  g_xh);
    cudaGetSymbolAddress((void**)&pqkv, g_qkv);
    cudaGetSymbolAddress((void**)&pct,  g_ct);
    cudaGetSymbolAddress((void**)&pt,   g_t);
    cudaGetSymbolAddress((void**)&pvt,  g_vt);
    cudaGetSymbolAddress((void**)&psch, g_sch);
    cudaGetSymbolAddress((void**)&prs,  g_rs);
    cudaGetSymbolAddress((void**)&pffh, g_ffh);
    cudaGetSymbolAddress((void**)&pwT,  g_wTh);
    cudaGetSymbolAddress((void**)&pb3,  g_b3);

    const int*   src = (const int*)  d_in[0];
    const float* emb = (const float*)d_in[2];
    const float* Wq  = (const float*)d_in[3];
    const float* bq  = (const float*)d_in[4];
    const float* Wk  = (const float*)d_in[5];
    const float* bk  = (const float*)d_in[6];
    const float* Wv  = (const float*)d_in[7];
    const float* bv  = (const float*)d_in[8];
    const float* Wo  = (const float*)d_in[9];
    const float* bo  = (const float*)d_in[10];
    const float* W1  = (const float*)d_in[11];
    const float* b1  = (const float*)d_in[12];
    const float* W2  = (const float*)d_in[13];
    const float* b2  = (const float*)d_in[14];
    const float* g1  = (const float*)d_in[15];
    const float* be1 = (const float*)d_in[16];
    const float* g2  = (const float*)d_in[17];
    const float* be2 = (const float*)d_in[18];
    const float* gf  = (const float*)d_in[19];
    const float* bf  = (const float*)d_in[20];
    float* out = (float*)d_out;

    // one-shot weight transposes -> fp16 [N][K]; Wq scaled by 1/32
    dim3 tb(32, 8);
    transpose_mat_h<<<dim3(HH/32,  HH/32,  LL), tb>>>(Wq, pwT + QKVT,               HH, HH, 3L*HH*HH, 1.0f/32.0f);
    transpose_mat_h<<<dim3(HH/32,  HH/32,  LL), tb>>>(Wk, pwT + QKVT + (long)HH*HH, HH, HH, 3L*HH*HH, 1.0f);
    transpose_mat_h<<<dim3(HH/32,  HH/32,  LL), tb>>>(Wv, pwT + QKVT + 2L*HH*HH,    HH, HH, 3L*HH*HH, 1.0f);
    transpose_mat_h<<<dim3(HH/32,  HH/32,  LL), tb>>>(Wo, pwT + WOT, HH,  HH,  (long)HH*HH,  1.0f);
    transpose_mat_h<<<dim3(FFD/32, HH/32,  LL), tb>>>(W1, pwT + W1T, HH,  FFD, (long)HH*FFD, 1.0f);
    transpose_mat_h<<<dim3(HH/32,  FFD/32, LL), tb>>>(W2, pwT + W2T, FFD, HH,  (long)FFD*HH, 1.0f);
    pack_b3<<<(LL*3*HH + 255)/256, 256>>>(bq, bk, bv, pb3);

    embed_pe<<<MR, 256>>>(src, emb, px, pxh);

    const dim3 gQKV (3*HH / 128, MR / 128, 1);  // (24, 64)
    const dim3 gProj(HH / 128,   MR / 128, 1);  // (8, 64)
    const dim3 gFF1 (FFD / 128,  MR / 128, 1);  // (32, 64)
    const dim3 gAttn(SS / 128,   SS / 128, BB); // (8, 8, 8)
    const dim3 gCtx (HH / 128,   SS / 128, BB); // (8, 8, 8)

    for (int l = 0; l < LL; l++) {
        const __half* qkvT = pwT + QKVT + (long)l * 3 * HH * HH;
        const __half* woT  = pwT + WOT  + (long)l * HH * HH;
        const __half* w1T  = pwT + W1T  + (long)l * HH * FFD;
        const __half* w2T  = pwT + W2T  + (long)l * FFD * HH;
        const float* b3L = pb3 + (long)l * 3 * HH;
        const float* boL = bo + (long)l * HH;
        const float* b1L = b1 + (long)l * FFD;
        const float* b2L = b2 + (long)l * HH;
        const float* g1L = g1 + (long)l * HH;  const float* be1L = be1 + (long)l * HH;
        const float* g2L = g2 + (long)l * HH;  const float* be2L = be2 + (long)l * HH;

        // fused qkv = x @ [Wq/32|Wk|Wv]^T + [bq/32|bk|bv]   (fp16, packed rows)
        gemmh<1><<<gQKV, 256, GEMM_SMEM>>>(pxh, 0, HH, qkvT, 0, HH, b3L,
                                           nullptr, 0, pqkv, 0, 3*HH, HH, 1.0f);

        // vT[b][h][s]
        transpose_v_h<<<dim3(HH/32, SS/32, BB), tb>>>(pqkv, pvt);

        // probs~[b] = exp(Q_b @ K_b^T - 4) -> fp16 (fused softmax numerator)
        gemmh<3><<<gAttn, 256, GEMM_SMEM>>>(pqkv,      3*HH, BB*3*HH,
                                            pqkv + HH, 3*HH, BB*3*HH, nullptr,
                                            nullptr, 0,
                                            psch, (long)SS*SS, SS, HH, 1.0f);
        rowsum_inv<<<BB*SS, 256>>>(psch, prs);

        // ctx[b] = (P~_b @ V_b) * rsinv  -> fp16 (S,B,H)
        gemmh<4><<<gCtx, 256, GEMM_SMEM>>>(psch, (long)SS*SS, SS,
                                           pvt, (long)HH*SS, SS, nullptr,
                                           prs, SS,
                                           pct, HH, BB*HH, SS, 1.0f);

        // src2 = ctx Wo + bo (fp32) ; x = LN(x + src2)
        gemmh<0><<<gProj, 256, GEMM_SMEM>>>(pct, 0, HH, woT, 0, HH, boL,
                                            nullptr, 0, pt, 0, HH, HH, 1.0f);
        add_ln<<<MR, 256>>>(px, pt, g1L, be1L, px, pxh);

        // ff = relu(x W1 + b1) fp16 ; ff2 = ff W2 + b2 fp32 ; x = LN(x + ff2)
        gemmh<2><<<gFF1, 256, GEMM_SMEM>>>(pxh, 0, HH, w1T, 0, HH, b1L,
                                           nullptr, 0, pffh, 0, FFD, HH, 1.0f);
        gemmh<0><<<gProj, 256, GEMM_SMEM>>>(pffh, 0, FFD, w2T, 0, FFD, b2L,
                                            nullptr, 0, pt, 0, HH, FFD, 1.0f);
        add_ln<<<MR, 256>>>(px, pt, g2L, be2L, px, pxh);
    }

    add_ln<<<MR, 256>>>(px, nullptr, gf, bf, out, nullptr);
}